// round 2
// baseline (speedup 1.0000x reference)
#include <cuda_runtime.h>
#include <math.h>

#define BB 16
#define TT 64
#define DD 2304
#define HH 2304
#define GG 9216
#define EE 768
#define LANES 32
#define MAXS 32
#define NSTEPS 31

// Scratch (device globals; no runtime allocation allowed)
__device__ float g_seq[LANES * MAXS * DD];                 // gathered inputs  (9.4 MB)
__device__ float g_xp [LANES * MAXS * GG];                 // precomputed x@W_ih^T + bias (37.7 MB)
__device__ float g_h[2][LANES * HH];                       // double-buffered hidden state
__device__ float g_c[LANES * HH];                          // cell state
__device__ int   g_len[LANES];
__device__ int   g_length[BB];
__device__ int   g_maxlen;
__device__ int   g_rows[LANES * MAXS];                     // packed (lane<<5)|t for valid rows
__device__ int   g_nrows;

// ---------------------------------------------------------------------------
// Kernel 0: lengths, row list, zero states
// ---------------------------------------------------------------------------
__global__ void k_prep(const int* __restrict__ mask,
                       const int* __restrict__ start,
                       const int* __restrict__ end) {
    int tid = threadIdx.x;
    __shared__ int s_len[LANES];
    if (tid < BB) {
        int L = 0;
        for (int t = 0; t < TT; t++) L += mask[tid * TT + t];
        g_length[tid] = L;
        int ll = start[tid] - 1; if (ll < 1) ll = 1;
        int rl = L - end[tid];   if (rl < 1) rl = 1;
        s_len[tid]      = ll;  s_len[BB + tid] = rl;
        g_len[tid]      = ll;  g_len[BB + tid] = rl;
    }
    __syncthreads();
    if (tid == 0) {
        int m = 0, n = 0;
        for (int lane = 0; lane < LANES; lane++) {
            int l = s_len[lane];
            if (l > m) m = l;
            for (int t = 0; t < l; t++) g_rows[n++] = (lane << 5) | t;
        }
        g_maxlen = m;
        g_nrows  = n;
    }
    for (int i = tid; i < LANES * HH; i += blockDim.x) {
        g_h[0][i] = 0.f;
        g_h[1][i] = 0.f;
        g_c[i]    = 0.f;
    }
}

// ---------------------------------------------------------------------------
// Kernel 1: gather left/right sequences (zero-padded), lanes 0..15 left, 16..31 right
// ---------------------------------------------------------------------------
__global__ void k_gather(const float* __restrict__ feat,
                         const int* __restrict__ start,
                         const int* __restrict__ end) {
    int t = blockIdx.x, lane = blockIdx.y;
    if (t >= g_len[lane]) return;
    const float* src = nullptr;
    if (lane < BB) {
        int b = lane;
        if (t + 1 < start[b]) src = feat + ((size_t)b * TT + (t + 1)) * DD;
    } else {
        int b = lane - BB;
        int raw = g_length[b] - end[b];
        if (t < raw) src = feat + ((size_t)b * TT + (end[b] + t)) * DD;
    }
    float4* dst = (float4*)(g_seq + ((size_t)lane * MAXS + t) * DD);
    const float4* s4 = (const float4*)src;
    float4 z = make_float4(0.f, 0.f, 0.f, 0.f);
    for (int i = threadIdx.x; i < DD / 4; i += blockDim.x)
        dst[i] = src ? s4[i] : z;
}

// ---------------------------------------------------------------------------
// Kernel 2: xp GEMM over compact valid-row list.
// M = nrows (<=992, tiled by 128), N = 9216 (tiled by 128), K = 2304 (tiled by 16).
// 256 threads, 8x8 per-thread microtile, float4 smem reads.
// ---------------------------------------------------------------------------
__global__ void __launch_bounds__(256) k_xp(const float* __restrict__ W_ih,
                                            const float* __restrict__ b_ih,
                                            const float* __restrict__ b_hh) {
    int nrows = g_nrows;
    int m0 = blockIdx.y * 128;
    if (m0 >= nrows) return;
    int n0 = blockIdx.x * 128;
    int tid = threadIdx.x;

    __shared__ __align__(16) float As[16 * 132];
    __shared__ __align__(16) float Bs[16 * 132];
    __shared__ int inoff[128];
    __shared__ int outoff[128];

    if (tid < 128) {
        int m  = m0 + tid;
        int rc = (m < nrows) ? g_rows[m] : 0;
        int lane = rc >> 5, t = rc & 31;
        inoff[tid]  = (lane * MAXS + t) * DD;
        outoff[tid] = (lane * MAXS + t) * GG;
    }
    __syncthreads();

    float acc[8][8];
#pragma unroll
    for (int r = 0; r < 8; r++)
#pragma unroll
        for (int c = 0; c < 8; c++) acc[r][c] = 0.f;

    int ty = tid >> 4, tx = tid & 15;

    for (int k0 = 0; k0 < DD; k0 += 16) {
#pragma unroll
        for (int i = 0; i < 2; i++) {
            int flat = tid + i * 256;        // 0..511
            int m = flat >> 2, kq = flat & 3;
            float4 v = *(const float4*)(g_seq + inoff[m] + k0 + kq * 4);
            As[(kq * 4 + 0) * 132 + m] = v.x;
            As[(kq * 4 + 1) * 132 + m] = v.y;
            As[(kq * 4 + 2) * 132 + m] = v.z;
            As[(kq * 4 + 3) * 132 + m] = v.w;
            float4 w = *(const float4*)(W_ih + (size_t)(n0 + m) * DD + k0 + kq * 4);
            Bs[(kq * 4 + 0) * 132 + m] = w.x;
            Bs[(kq * 4 + 1) * 132 + m] = w.y;
            Bs[(kq * 4 + 2) * 132 + m] = w.z;
            Bs[(kq * 4 + 3) * 132 + m] = w.w;
        }
        __syncthreads();
#pragma unroll
        for (int k = 0; k < 16; k++) {
            float4 a0 = *(const float4*)&As[k * 132 + ty * 8];
            float4 a1 = *(const float4*)&As[k * 132 + ty * 8 + 4];
            float4 b0 = *(const float4*)&Bs[k * 132 + tx * 8];
            float4 b1 = *(const float4*)&Bs[k * 132 + tx * 8 + 4];
            float av[8] = {a0.x, a0.y, a0.z, a0.w, a1.x, a1.y, a1.z, a1.w};
            float bv[8] = {b0.x, b0.y, b0.z, b0.w, b1.x, b1.y, b1.z, b1.w};
#pragma unroll
            for (int r = 0; r < 8; r++)
#pragma unroll
                for (int c = 0; c < 8; c++) acc[r][c] += av[r] * bv[c];
        }
        __syncthreads();
    }

#pragma unroll
    for (int r = 0; r < 8; r++) {
        int m = m0 + ty * 8 + r;
        if (m >= nrows) continue;
        int oo = outoff[ty * 8 + r];
#pragma unroll
        for (int c = 0; c < 8; c++) {
            int n = n0 + tx * 8 + c;
            g_xp[(size_t)oo + n] = acc[r][c] + b_ih[n] + b_hh[n];
        }
    }
}

// ---------------------------------------------------------------------------
// Kernel 3: one LSTM step. gates = xp[:,t,:] + h @ W_hh^T, then pointwise.
// Block: 16 hidden units (j) x all 4 gates x all 32 lanes. Grid: 144 blocks.
// h double-buffered across steps (read t&1, write (t&1)^1). Frozen lanes copy h.
// ---------------------------------------------------------------------------
__global__ void __launch_bounds__(128) k_step(int t, const float* __restrict__ W_hh) {
    if (t >= g_maxlen) return;
    int j0 = blockIdx.x * 16;
    int tid = threadIdx.x;
    int lg = tid >> 4;          // 0..7 lane group (4 lanes each)
    int jj = tid & 15;          // hidden unit within tile
    int rb = t & 1, wb = rb ^ 1;

    __shared__ __align__(16) float Hs[32 * 36];      // [k][lane], pad 36
    __shared__ float Ws[4 * 32 * 17];                // [gate][k][j], pad 17

    float acc[4][4];
#pragma unroll
    for (int g = 0; g < 4; g++)
#pragma unroll
        for (int l = 0; l < 4; l++) acc[g][l] = 0.f;

    const float* __restrict__ hsrc = g_h[rb];

    for (int k0 = 0; k0 < HH; k0 += 32) {
#pragma unroll
        for (int i = 0; i < 2; i++) {
            int flat = tid + i * 128;            // 0..255
            int lane = flat >> 3, kq = flat & 7;
            float4 v = *(const float4*)(hsrc + (size_t)lane * HH + k0 + kq * 4);
            Hs[(kq * 4 + 0) * 36 + lane] = v.x;
            Hs[(kq * 4 + 1) * 36 + lane] = v.y;
            Hs[(kq * 4 + 2) * 36 + lane] = v.z;
            Hs[(kq * 4 + 3) * 36 + lane] = v.w;
        }
#pragma unroll
        for (int i = 0; i < 4; i++) {
            int flat = tid + i * 128;            // 0..511
            int kq = flat & 7;
            int rest = flat >> 3;                // 0..63
            int j = rest & 15, gate = rest >> 4;
            float4 v = *(const float4*)(W_hh + (size_t)(gate * HH + j0 + j) * HH + k0 + kq * 4);
            Ws[(gate * 32 + kq * 4 + 0) * 17 + j] = v.x;
            Ws[(gate * 32 + kq * 4 + 1) * 17 + j] = v.y;
            Ws[(gate * 32 + kq * 4 + 2) * 17 + j] = v.z;
            Ws[(gate * 32 + kq * 4 + 3) * 17 + j] = v.w;
        }
        __syncthreads();
#pragma unroll
        for (int k = 0; k < 32; k++) {
            float4 hv = *(const float4*)&Hs[k * 36 + lg * 4];
#pragma unroll
            for (int g = 0; g < 4; g++) {
                float w = Ws[(g * 32 + k) * 17 + jj];
                acc[g][0] += hv.x * w;
                acc[g][1] += hv.y * w;
                acc[g][2] += hv.z * w;
                acc[g][3] += hv.w * w;
            }
        }
        __syncthreads();
    }

    int j = j0 + jj;
#pragma unroll
    for (int ls = 0; ls < 4; ls++) {
        int lane = lg * 4 + ls;
        size_t hidx = (size_t)lane * HH + j;
        float hn = hsrc[hidx];
        if (t < g_len[lane]) {
            const float* xp = g_xp + ((size_t)lane * MAXS + t) * GG;
            float gi  = acc[0][ls] + xp[j];
            float gf  = acc[1][ls] + xp[HH + j];
            float gg_ = acc[2][ls] + xp[2 * HH + j];
            float go  = acc[3][ls] + xp[3 * HH + j];
            float ii = 1.f / (1.f + expf(-gi));
            float ff = 1.f / (1.f + expf(-gf));
            float gt = tanhf(gg_);
            float oo = 1.f / (1.f + expf(-go));
            float c = ff * g_c[hidx] + ii * gt;
            g_c[hidx] = c;
            hn = oo * tanhf(c);
        }
        g_h[wb][hidx] = hn;
    }
}

// ---------------------------------------------------------------------------
// Kernel 4: out = [h_left ; h_right] @ W_out^T + b_out   (16 x 4608 x 768)
// ---------------------------------------------------------------------------
__global__ void __launch_bounds__(256) k_out(const float* __restrict__ W_out,
                                             const float* __restrict__ b_out,
                                             float* __restrict__ out) {
    int e0 = blockIdx.x * 64;
    int tid = threadIdx.x;
    int eL = tid & 63;
    int bg = tid >> 6;              // 0..3 -> batches bg*4..bg*4+3
    int fb = g_maxlen & 1;
    const float* __restrict__ hfin = g_h[fb];

    __shared__ __align__(16) float Fs[32 * 16];   // [k][b]
    __shared__ float Ws[64 * 33];                 // [e][k]

    float acc[4] = {0.f, 0.f, 0.f, 0.f};

    for (int k0 = 0; k0 < 2 * HH; k0 += 32) {
#pragma unroll
        for (int i = 0; i < 2; i++) {
            int flat = tid + i * 256;       // 0..511
            int b = flat & 15, k = flat >> 4;
            int kk = k0 + k;
            float v = (kk < HH) ? hfin[(size_t)b * HH + kk]
                                : hfin[(size_t)(BB + b) * HH + kk - HH];
            Fs[k * 16 + b] = v;
        }
#pragma unroll
        for (int i = 0; i < 8; i++) {
            int flat = tid + i * 256;       // 0..2047
            int e = flat >> 5, k = flat & 31;
            Ws[e * 33 + k] = W_out[(size_t)(e0 + e) * (2 * HH) + k0 + k];
        }
        __syncthreads();
#pragma unroll
        for (int k = 0; k < 32; k++) {
            float w = Ws[eL * 33 + k];
            float4 f = *(const float4*)&Fs[k * 16 + bg * 4];
            acc[0] += w * f.x;
            acc[1] += w * f.y;
            acc[2] += w * f.z;
            acc[3] += w * f.w;
        }
        __syncthreads();
    }

    int e = e0 + eL;
    float bo = b_out[e];
#pragma unroll
    for (int i = 0; i < 4; i++)
        out[(size_t)(bg * 4 + i) * EE + e] = acc[i] + bo;
}

// ---------------------------------------------------------------------------
extern "C" void kernel_launch(void* const* d_in, const int* in_sizes, int n_in,
                              void* d_out, int out_size) {
    const float* feat  = (const float*)d_in[0];
    const int*   mask  = (const int*)  d_in[1];
    const int*   start = (const int*)  d_in[2];
    const int*   end   = (const int*)  d_in[3];
    const float* W_ih  = (const float*)d_in[4];
    const float* W_hh  = (const float*)d_in[5];
    const float* b_ih  = (const float*)d_in[6];
    const float* b_hh  = (const float*)d_in[7];
    const float* W_out = (const float*)d_in[8];
    const float* b_out = (const float*)d_in[9];
    float* out = (float*)d_out;

    k_prep<<<1, 512>>>(mask, start, end);
    k_gather<<<dim3(MAXS, LANES), 256>>>(feat, start, end);
    k_xp<<<dim3(GG / 128, 8), 256>>>(W_ih, b_ih, b_hh);
    for (int t = 0; t < NSTEPS; t++)
        k_step<<<HH / 16, 128>>>(t, W_hh);
    k_out<<<EE / 64, 256>>>(W_out, b_out, out);
}